// round 11
// baseline (speedup 1.0000x reference)
#include <cuda_runtime.h>

// VideoEmbedding: out[n,d] = sum_k basis(t_n)[k] * W[vid_n, d, k]
// N=400000, D=64, K=13, V=128.
//
// SINGLE persistent kernel, single co-resident wave (G = occupancy-derived):
//  Phase A: weight transpose + per-block smem-rank histogram (ranks in regs)
//  barrier1
//  Phase S: block v scans video v's count row -> per-block bases (O(G*V))
//  barrier2
//  Phase C: own bases + 32-padded segment scan + scatter to g_sorted
//  barrier3
//  Phase B: warps own consecutive 32-chunk ranges; W[v] register-resident
//           (13 f32x2/lane); basis via __sincosf + double-angle recurrence
//           splatted to smem; inner: 6 broadcast LDS.128 + 13 f32x2 FMA +
//           coalesced STG.64.
//
// R10 lesson: __launch_bounds__(256,4) capped regs at 64 -> phase-B spills
// (L1=54%, fma=21.6%). Budget raised to 3 CTAs/SM (84 regs) — no spills.

static constexpr int D  = 64;
static constexpr int K  = 13;
static constexpr int MAXV = 256;
static constexpr int SORT_CAP = 1 << 20;
static constexpr int GMAX = 1024;
static constexpr int TPB  = 256;
static constexpr int NU   = 4;     // int4 slots per thread in phase A

__device__ float g_wt[MAXV * K * D];
__device__ int   g_cnt[MAXV * GMAX];    // [v][b]
__device__ int   g_base[GMAX * MAXV];   // [b][v] scatter bases (pre-segoff)
__device__ int   g_segtot[MAXV];
__device__ int   g_sorted[SORT_CAP];    // never-written pad slots stay 0
__device__ int   g_bar, g_fin;

typedef unsigned long long ull;

__device__ __forceinline__ ull ffma2u(ull a, ull b, ull c) {
    ull d;
    asm("fma.rn.f32x2 %0, %1, %2, %3;" : "=l"(d) : "l"(a), "l"(b), "l"(c));
    return d;
}
__device__ __forceinline__ ull fmul2u(ull a, ull b) {
    ull d;
    asm("mul.rn.f32x2 %0, %1, %2;" : "=l"(d) : "l"(a), "l"(b));
    return d;
}
__device__ __forceinline__ ull fadd2u(ull a, ull b) {
    ull d;
    asm("add.rn.f32x2 %0, %1, %2;" : "=l"(d) : "l"(a), "l"(b));
    return d;
}
__device__ __forceinline__ ull splat2(float x) {
    ull r;
    asm("mov.b64 %0, {%1, %1};" : "=l"(r) : "f"(x));
    return r;
}

__device__ __forceinline__ void grid_barrier(int tid, int target) {
    __threadfence();
    __syncthreads();
    if (tid == 0) {
        atomicAdd(&g_bar, 1);
        volatile int* vb = &g_bar;
        while (*vb < target) __nanosleep(32);
    }
    __syncthreads();
}

__global__ void __launch_bounds__(TPB, 3)
k_all(const float* __restrict__ w, const int* __restrict__ vids,
      const float* __restrict__ times, float* __restrict__ out,
      int N, int V, int tile, int G) {
    __shared__ int s_rk[MAXV];        // rank counters -> scan scratch
    __shared__ int s_base[MAXV];      // this block's scatter bases
    __shared__ int s_start[MAXV + 1]; // padded segment starts (+ total)
    __shared__ int s_end[MAXV];       // real segment ends
    __shared__ __align__(16) ull smb[8][32 * 12];  // basis staging / scratch
    __shared__ int sidx[8][32];

    const int tid = threadIdx.x, b = blockIdx.x;
    for (int i = tid; i < MAXV; i += TPB) s_rk[i] = 0;
    __syncthreads();

    // ---- Phase A: transpose [v][d][k] -> [v][k][d] ----
    const int total = V * D * K;
    for (int i = b * TPB + tid; i < total; i += G * TPB) {
        int k = i % K;
        int d = (i / K) % D;
        int v = i / (K * D);
        g_wt[(v * K + k) * D + d] = w[i];
    }

    // ---- Phase A: histogram, ranks held in registers ----
    const int start = b * tile;               // tile is 4-aligned
    const int end   = min(start + tile, N);
    const int s4 = start >> 2, e4 = end >> 2;
    int4 q[NU]; int rk[NU][4]; bool hv[NU];
#pragma unroll
    for (int u = 0; u < NU; u++) {
        const int i4 = s4 + u * TPB + tid;
        hv[u] = (i4 < e4);
        if (hv[u]) {
            q[u] = reinterpret_cast<const int4*>(vids)[i4];
            rk[u][0] = atomicAdd(&s_rk[q[u].x], 1);
            rk[u][1] = atomicAdd(&s_rk[q[u].y], 1);
            rk[u][2] = atomicAdd(&s_rk[q[u].z], 1);
            rk[u][3] = atomicAdd(&s_rk[q[u].w], 1);
        }
    }
    int tval = -1, trk = 0;
    const int ti = (e4 << 2) + tid;
    if (ti < end) { tval = vids[ti]; trk = atomicAdd(&s_rk[tval], 1); }
    __syncthreads();

    for (int i = tid; i < V; i += TPB)
        g_cnt[i * GMAX + b] = s_rk[i];

    grid_barrier(tid, G);

    // ---- Phase S: block v scans video v's count row (cooperative) ----
    int* s_scan = reinterpret_cast<int*>(smb);   // 256 ints of scratch
    for (int v = b; v < V; v += G) {
        int4 c = make_int4(0, 0, 0, 0);
        const int bb = tid * 4;
        if (bb < G)
            c = *reinterpret_cast<const int4*>(g_cnt + v * GMAX + bb);
        const int lsum = c.x + c.y + c.z + c.w;
        s_scan[tid] = lsum;
        __syncthreads();
        for (int s = 1; s < TPB; s <<= 1) {       // inclusive block scan
            int a = (tid >= s) ? s_scan[tid - s] : 0;
            __syncthreads();
            s_scan[tid] += a;
            __syncthreads();
        }
        int excl = s_scan[tid] - lsum;
        if (bb < G) {
            g_base[(bb    ) * MAXV + v] = excl;
            g_base[(bb + 1) * MAXV + v] = excl + c.x;
            g_base[(bb + 2) * MAXV + v] = excl + c.x + c.y;
            g_base[(bb + 3) * MAXV + v] = excl + c.x + c.y + c.z;
        }
        if (tid == TPB - 1) g_segtot[v] = s_scan[tid];
        __syncthreads();
    }

    grid_barrier(tid, 2 * G);

    // ---- Phase C: own bases + padded segment scan + scatter ----
    int totv = 0;
    if (tid < MAXV) {
        totv = (tid < V) ? g_segtot[tid] : 0;
        s_rk[tid] = (totv + 31) & ~31;
    }
    __syncthreads();
    for (int s = 1; s < MAXV; s <<= 1) {          // inclusive scan over videos
        int a = (tid < MAXV && tid >= s) ? s_rk[tid - s] : 0;
        __syncthreads();
        if (tid < MAXV) s_rk[tid] += a;
        __syncthreads();
    }
    if (tid < MAXV) {
        const int pad = (totv + 31) & ~31;
        const int segoff = s_rk[tid] - pad;       // exclusive padded offset
        s_start[tid] = segoff;
        s_end[tid]   = segoff + totv;
        if (tid < V) s_base[tid] = segoff + g_base[b * MAXV + tid];
        if (tid == MAXV - 1) s_start[MAXV] = s_rk[tid];
    }
    __syncthreads();
    const int NC = s_start[MAXV] >> 5;

#pragma unroll
    for (int u = 0; u < NU; u++) {
        if (hv[u]) {
            const int base = (s4 + u * TPB + tid) << 2;
            g_sorted[s_base[q[u].x] + rk[u][0]] = base;
            g_sorted[s_base[q[u].y] + rk[u][1]] = base + 1;
            g_sorted[s_base[q[u].z] + rk[u][2]] = base + 2;
            g_sorted[s_base[q[u].w] + rk[u][3]] = base + 3;
        }
    }
    if (tval >= 0) g_sorted[s_base[tval] + trk] = ti;

    grid_barrier(tid, 3 * G);

    // ---- Phase B: main compute ----
    const int lane = tid & 31;
    const int wib  = tid >> 5;
    const int gwarp = b * 8 + wib;
    const int TW = G * 8;
    const int L = (NC + TW - 1) / TW;
    const int cbeg = gwarp * L;
    const int cend = min(cbeg + L, NC);

    if (cbeg < cend) {
        int v = 0;
        {
            const int pos = cbeg * 32;
#pragma unroll
            for (int step = 128; step; step >>= 1) {
                const int nv = v + step;
                if (nv <= MAXV - 1 && s_start[nv] <= pos) v = nv;
            }
        }
        int vprev = -1;
        ull wreg[K];

        for (int c = cbeg; c < cend; c++) {
            const int pos = c * 32;
            while (pos >= s_start[v + 1]) v++;     // warp-uniform walk

            const int idx = g_sorted[pos + lane];  // pad slots are 0 (valid)
            if (v != vprev) {
                const float* wp = g_wt + v * (K * D) + 2 * lane;
#pragma unroll
                for (int k = 0; k < K; k++)
                    wreg[k] = *reinterpret_cast<const ull*>(wp + k * D);
                vprev = v;
            }

            const float t = times[idx];
            const float a = t * 3.14159265358979323846f;
            float s1, q1; __sincosf(a, &s1, &q1);
            const float s2 = 2.f * s1 * q1, q2 = fmaf(q1, q1, -s1 * s1);
            const float s3 = 2.f * s2 * q2, q3 = fmaf(q2, q2, -s2 * s2);
            const float s4b = 2.f * s3 * q3, q4 = fmaf(q3, q3, -s3 * s3);
            const float s5 = 2.f * s4b * q4, q5 = fmaf(q4, q4, -s4b * s4b);
            const float s6 = 2.f * s5 * q5, q6 = fmaf(q5, q5, -s5 * s5);

            ulonglong2* bl =
                reinterpret_cast<ulonglong2*>(&smb[wib][lane * 12]);
            bl[0] = make_ulonglong2(splat2(s1), splat2(s2));
            bl[1] = make_ulonglong2(splat2(s3), splat2(s4b));
            bl[2] = make_ulonglong2(splat2(s5), splat2(s6));
            bl[3] = make_ulonglong2(splat2(q1), splat2(q2));
            bl[4] = make_ulonglong2(splat2(q3), splat2(q4));
            bl[5] = make_ulonglong2(splat2(q5), splat2(q6));
            sidx[wib][lane] = idx;
            __syncwarp();

            const int jmax = min(32, s_end[v] - pos);   // >= 1, warp-uniform
            for (int j = 0; j < jmax; j++) {
                const int nn = sidx[wib][j];
                const ulonglong2* bj =
                    reinterpret_cast<const ulonglong2*>(&smb[wib][j * 12]);
                const ulonglong2 P0 = bj[0], P1 = bj[1], P2 = bj[2];
                const ulonglong2 P3 = bj[3], P4 = bj[4], P5 = bj[5];
                ull a0 = ffma2u(P0.x, wreg[1], wreg[0]);  // basis[0]==1
                ull a1 = fmul2u(P0.y, wreg[2]);
                a0 = ffma2u(P1.x, wreg[3],  a0);
                a1 = ffma2u(P1.y, wreg[4],  a1);
                a0 = ffma2u(P2.x, wreg[5],  a0);
                a1 = ffma2u(P2.y, wreg[6],  a1);
                a0 = ffma2u(P3.x, wreg[7],  a0);
                a1 = ffma2u(P3.y, wreg[8],  a1);
                a0 = ffma2u(P4.x, wreg[9],  a0);
                a1 = ffma2u(P4.y, wreg[10], a1);
                a0 = ffma2u(P5.x, wreg[11], a0);
                a1 = ffma2u(P5.y, wreg[12], a1);
                *reinterpret_cast<ull*>(out + (long)nn * D + 2 * lane) =
                    fadd2u(a0, a1);
            }
            __syncwarp();
        }
    }

    // ---- exit ticket: reset barrier counters for next graph replay ----
    __threadfence();
    if (tid == 0) {
        if (atomicAdd(&g_fin, 1) == G - 1) { g_bar = 0; g_fin = 0; }
    }
}

extern "C" void kernel_launch(void* const* d_in, const int* in_sizes, int n_in,
                              void* d_out, int out_size) {
    const float* times   = (const float*)d_in[0];
    const int*   vids    = (const int*)d_in[1];
    const float* weights = (const float*)d_in[2];
    float*       out     = (float*)d_out;

    const int N = in_sizes[0];
    int V = in_sizes[2] / (D * K);
    if (V > MAXV) V = MAXV;

    int dev = 0;
    cudaGetDevice(&dev);
    int sms = 148;
    cudaDeviceGetAttribute(&sms, cudaDevAttrMultiProcessorCount, dev);
    int nb = 0;
    cudaOccupancyMaxActiveBlocksPerMultiprocessor(&nb, k_all, TPB, 0);
    if (nb < 1) nb = 1;
    int G = nb * sms;
    if (G > GMAX) G = GMAX;
    G &= ~3;                                  // multiple of 4 (int4 row reads)

    const int tile = (((N + G - 1) / G) + 3) & ~3;   // 4-aligned
    k_all<<<G, TPB>>>(weights, vids, times, out, N, V, tile, G);
}

// round 12
// speedup vs baseline: 1.1123x; 1.1123x over previous
#include <cuda_runtime.h>

// VideoEmbedding: out[n,d] = sum_k basis(t_n)[k] * W[vid_n, d, k]
// N=400000, D=64, K=13, V=128.
//
// SINGLE persistent kernel, single co-resident wave:
//  Phase A: weight transpose + per-block smem-rank histogram (ranks in regs)
//  barrier1
//  Phase S: block v scans video v's count row -> per-block bases (O(G*V))
//  barrier2
//  Phase C: own bases + 32-padded segment scan + scatter to g_sorted
//  barrier3
//  Phase B: half-warp scheme — lane owns 4 output cols (4*(lane&15)),
//           halves take alternate j. Basis stays in REGISTERS and is
//           broadcast via __shfl_sync (R11 post-mortem: the smem splat
//           broadcast cost ~27 L1 wavefronts/n = the entire bottleneck).
//           Inner loop: 13 shfl + 12 splats + 28 wide f32x2 FMA + STG.128.

static constexpr int D  = 64;
static constexpr int K  = 13;
static constexpr int MAXV = 256;
static constexpr int SORT_CAP = 1 << 20;
static constexpr int GMAX = 1024;
static constexpr int TPB  = 256;
static constexpr int NU   = 4;     // int4 slots per thread in phase A

__device__ float g_wt[MAXV * K * D];
__device__ int   g_cnt[MAXV * GMAX];    // [v][b]
__device__ int   g_base[GMAX * MAXV];   // [b][v] scatter bases (pre-segoff)
__device__ int   g_segtot[MAXV];
__device__ int   g_sorted[SORT_CAP];    // never-written pad slots stay 0
__device__ int   g_bar, g_fin;

typedef unsigned long long ull;

__device__ __forceinline__ ull ffma2u(ull a, ull b, ull c) {
    ull d;
    asm("fma.rn.f32x2 %0, %1, %2, %3;" : "=l"(d) : "l"(a), "l"(b), "l"(c));
    return d;
}
__device__ __forceinline__ ull fmul2u(ull a, ull b) {
    ull d;
    asm("mul.rn.f32x2 %0, %1, %2;" : "=l"(d) : "l"(a), "l"(b));
    return d;
}
__device__ __forceinline__ ull fadd2u(ull a, ull b) {
    ull d;
    asm("add.rn.f32x2 %0, %1, %2;" : "=l"(d) : "l"(a), "l"(b));
    return d;
}
__device__ __forceinline__ ull splat2(float x) {
    ull r;
    asm("mov.b64 %0, {%1, %1};" : "=l"(r) : "f"(x));
    return r;
}

__device__ __forceinline__ void grid_barrier(int tid, int target) {
    __threadfence();
    __syncthreads();
    if (tid == 0) {
        atomicAdd(&g_bar, 1);
        volatile int* vb = &g_bar;
        while (*vb < target) __nanosleep(32);
    }
    __syncthreads();
}

__global__ void __launch_bounds__(TPB, 2)
k_all(const float* __restrict__ w, const int* __restrict__ vids,
      const float* __restrict__ times, float* __restrict__ out,
      int N, int V, int tile, int G) {
    __shared__ int s_rk[MAXV];        // rank counters -> scan scratch
    __shared__ int s_base[MAXV];      // this block's scatter bases
    __shared__ int s_start[MAXV + 1]; // padded segment starts (+ total)
    __shared__ int s_end[MAXV];       // real segment ends
    __shared__ int s_scan[TPB];       // phase-S block-scan scratch

    const int tid = threadIdx.x, b = blockIdx.x;
    for (int i = tid; i < MAXV; i += TPB) s_rk[i] = 0;
    __syncthreads();

    // ---- Phase A: transpose [v][d][k] -> [v][k][d] ----
    const int total = V * D * K;
    for (int i = b * TPB + tid; i < total; i += G * TPB) {
        int k = i % K;
        int d = (i / K) % D;
        int v = i / (K * D);
        g_wt[(v * K + k) * D + d] = w[i];
    }

    // ---- Phase A: histogram, ranks held in registers ----
    const int start = b * tile;               // tile is 4-aligned
    const int end   = min(start + tile, N);
    const int s4 = start >> 2, e4 = end >> 2;
    int4 q[NU]; int rk[NU][4]; bool hv[NU];
#pragma unroll
    for (int u = 0; u < NU; u++) {
        const int i4 = s4 + u * TPB + tid;
        hv[u] = (i4 < e4);
        if (hv[u]) {
            q[u] = reinterpret_cast<const int4*>(vids)[i4];
            rk[u][0] = atomicAdd(&s_rk[q[u].x], 1);
            rk[u][1] = atomicAdd(&s_rk[q[u].y], 1);
            rk[u][2] = atomicAdd(&s_rk[q[u].z], 1);
            rk[u][3] = atomicAdd(&s_rk[q[u].w], 1);
        }
    }
    int tval = -1, trk = 0;
    const int ti = (e4 << 2) + tid;
    if (ti < end) { tval = vids[ti]; trk = atomicAdd(&s_rk[tval], 1); }
    __syncthreads();

    for (int i = tid; i < V; i += TPB)
        g_cnt[i * GMAX + b] = s_rk[i];

    grid_barrier(tid, G);

    // ---- Phase S: block v scans video v's count row (cooperative) ----
    for (int v = b; v < V; v += G) {
        int4 c = make_int4(0, 0, 0, 0);
        const int bb = tid * 4;
        if (bb < G)
            c = *reinterpret_cast<const int4*>(g_cnt + v * GMAX + bb);
        const int lsum = c.x + c.y + c.z + c.w;
        s_scan[tid] = lsum;
        __syncthreads();
        for (int s = 1; s < TPB; s <<= 1) {       // inclusive block scan
            int a = (tid >= s) ? s_scan[tid - s] : 0;
            __syncthreads();
            s_scan[tid] += a;
            __syncthreads();
        }
        int excl = s_scan[tid] - lsum;
        if (bb < G) {
            g_base[(bb    ) * MAXV + v] = excl;
            g_base[(bb + 1) * MAXV + v] = excl + c.x;
            g_base[(bb + 2) * MAXV + v] = excl + c.x + c.y;
            g_base[(bb + 3) * MAXV + v] = excl + c.x + c.y + c.z;
        }
        if (tid == TPB - 1) g_segtot[v] = s_scan[tid];
        __syncthreads();
    }

    grid_barrier(tid, 2 * G);

    // ---- Phase C: own bases + padded segment scan + scatter ----
    int totv = 0;
    if (tid < MAXV) {
        totv = (tid < V) ? g_segtot[tid] : 0;
        s_rk[tid] = (totv + 31) & ~31;
    }
    __syncthreads();
    for (int s = 1; s < MAXV; s <<= 1) {          // inclusive scan over videos
        int a = (tid < MAXV && tid >= s) ? s_rk[tid - s] : 0;
        __syncthreads();
        if (tid < MAXV) s_rk[tid] += a;
        __syncthreads();
    }
    if (tid < MAXV) {
        const int pad = (totv + 31) & ~31;
        const int segoff = s_rk[tid] - pad;       // exclusive padded offset
        s_start[tid] = segoff;
        s_end[tid]   = segoff + totv;
        if (tid < V) s_base[tid] = segoff + g_base[b * MAXV + tid];
        if (tid == MAXV - 1) s_start[MAXV] = s_rk[tid];
    }
    __syncthreads();
    const int NC = s_start[MAXV] >> 5;

#pragma unroll
    for (int u = 0; u < NU; u++) {
        if (hv[u]) {
            const int base = (s4 + u * TPB + tid) << 2;
            g_sorted[s_base[q[u].x] + rk[u][0]] = base;
            g_sorted[s_base[q[u].y] + rk[u][1]] = base + 1;
            g_sorted[s_base[q[u].z] + rk[u][2]] = base + 2;
            g_sorted[s_base[q[u].w] + rk[u][3]] = base + 3;
        }
    }
    if (tval >= 0) g_sorted[s_base[tval] + trk] = ti;

    grid_barrier(tid, 3 * G);

    // ---- Phase B: half-warp, 4 cols/lane, shfl-broadcast basis ----
    const int lane = tid & 31;
    const int wib  = tid >> 5;
    const int half = lane >> 4;            // 0: even j, 1: odd j
    const int c4   = (lane & 15) * 4;      // 4 owned output columns
    const int gwarp = b * 8 + wib;
    const int TW = G * 8;
    const int L = (NC + TW - 1) / TW;
    const int cbeg = gwarp * L;
    const int cend = min(cbeg + L, NC);

    if (cbeg < cend) {
        int v = 0;
        {
            const int pos = cbeg * 32;
#pragma unroll
            for (int step = 128; step; step >>= 1) {
                const int nv = v + step;
                if (nv <= MAXV - 1 && s_start[nv] <= pos) v = nv;
            }
        }
        int vprev = -1;
        ull wA[K], wB[K];

        for (int c = cbeg; c < cend; c++) {
            const int pos = c * 32;
            while (pos >= s_start[v + 1]) v++;     // warp-uniform walk

            const int idx = g_sorted[pos + lane];  // pad slots are 0 (valid)
            if (v != vprev) {
                const float* wp = g_wt + v * (K * D) + c4;
#pragma unroll
                for (int k = 0; k < K; k++) {
                    ulonglong2 u =
                        *reinterpret_cast<const ulonglong2*>(wp + k * D);
                    wA[k] = u.x; wB[k] = u.y;
                }
                vprev = v;
            }

            // basis for this lane's own n, kept in registers
            const float t = times[idx];
            const float ang = t * 3.14159265358979323846f;
            float s1, q1; __sincosf(ang, &s1, &q1);
            const float s2 = 2.f * s1 * q1, q2 = fmaf(q1, q1, -s1 * s1);
            const float s3 = 2.f * s2 * q2, q3 = fmaf(q2, q2, -s2 * s2);
            const float s4b = 2.f * s3 * q3, q4 = fmaf(q3, q3, -s3 * s3);
            const float s5 = 2.f * s4b * q4, q5 = fmaf(q4, q4, -s4b * s4b);
            const float s6 = 2.f * s5 * q5, q6 = fmaf(q5, q5, -s5 * s5);

            const int jmax  = min(32, s_end[v] - pos);   // >= 1, warp-uniform
            const int jpmax = (jmax + 1) >> 1;
            for (int jp = 0; jp < jpmax; jp++) {
                const int j0 = 2 * jp + half;            // per-half source n
                const unsigned m = 0xffffffffu;
                const int nn = __shfl_sync(m, idx, j0);
                const ull B1  = splat2(__shfl_sync(m, s1,  j0));
                const ull B2  = splat2(__shfl_sync(m, s2,  j0));
                const ull B3  = splat2(__shfl_sync(m, s3,  j0));
                const ull B4  = splat2(__shfl_sync(m, s4b, j0));
                const ull B5  = splat2(__shfl_sync(m, s5,  j0));
                const ull B6  = splat2(__shfl_sync(m, s6,  j0));
                const ull B7  = splat2(__shfl_sync(m, q1,  j0));
                const ull B8  = splat2(__shfl_sync(m, q2,  j0));
                const ull B9  = splat2(__shfl_sync(m, q3,  j0));
                const ull B10 = splat2(__shfl_sync(m, q4,  j0));
                const ull B11 = splat2(__shfl_sync(m, q5,  j0));
                const ull B12 = splat2(__shfl_sync(m, q6,  j0));

                ull a0 = ffma2u(B1, wA[1], wA[0]);       // basis[0] == 1
                ull a1 = fmul2u(B2, wA[2]);
                a0 = ffma2u(B3,  wA[3],  a0);
                a1 = ffma2u(B4,  wA[4],  a1);
                a0 = ffma2u(B5,  wA[5],  a0);
                a1 = ffma2u(B6,  wA[6],  a1);
                a0 = ffma2u(B7,  wA[7],  a0);
                a1 = ffma2u(B8,  wA[8],  a1);
                a0 = ffma2u(B9,  wA[9],  a0);
                a1 = ffma2u(B10, wA[10], a1);
                a0 = ffma2u(B11, wA[11], a0);
                a1 = ffma2u(B12, wA[12], a1);
                ull b0 = ffma2u(B1, wB[1], wB[0]);
                ull b1 = fmul2u(B2, wB[2]);
                b0 = ffma2u(B3,  wB[3],  b0);
                b1 = ffma2u(B4,  wB[4],  b1);
                b0 = ffma2u(B5,  wB[5],  b0);
                b1 = ffma2u(B6,  wB[6],  b1);
                b0 = ffma2u(B7,  wB[7],  b0);
                b1 = ffma2u(B8,  wB[8],  b1);
                b0 = ffma2u(B9,  wB[9],  b0);
                b1 = ffma2u(B10, wB[10], b1);
                b0 = ffma2u(B11, wB[11], b0);
                b1 = ffma2u(B12, wB[12], b1);
                if (j0 < jmax) {
                    *reinterpret_cast<ulonglong2*>(out + (long)nn * D + c4) =
                        make_ulonglong2(fadd2u(a0, a1), fadd2u(b0, b1));
                }
            }
        }
    }

    // ---- exit ticket: reset barrier counters for next graph replay ----
    __threadfence();
    if (tid == 0) {
        if (atomicAdd(&g_fin, 1) == G - 1) { g_bar = 0; g_fin = 0; }
    }
}

extern "C" void kernel_launch(void* const* d_in, const int* in_sizes, int n_in,
                              void* d_out, int out_size) {
    const float* times   = (const float*)d_in[0];
    const int*   vids    = (const int*)d_in[1];
    const float* weights = (const float*)d_in[2];
    float*       out     = (float*)d_out;

    const int N = in_sizes[0];
    int V = in_sizes[2] / (D * K);
    if (V > MAXV) V = MAXV;

    int dev = 0;
    cudaGetDevice(&dev);
    int sms = 148;
    cudaDeviceGetAttribute(&sms, cudaDevAttrMultiProcessorCount, dev);
    int nb = 0;
    cudaOccupancyMaxActiveBlocksPerMultiprocessor(&nb, k_all, TPB, 0);
    if (nb < 1) nb = 1;
    int G = nb * sms;
    if (G > GMAX) G = GMAX;
    G &= ~3;                                  // multiple of 4 (int4 row reads)

    const int tile = (((N + G - 1) / G) + 3) & ~3;   // 4-aligned
    k_all<<<G, TPB>>>(weights, vids, times, out, N, V, tile, G);
}

// round 13
// speedup vs baseline: 1.1472x; 1.0314x over previous
#include <cuda_runtime.h>

// VideoEmbedding: out[n,d] = sum_k basis(t_n)[k] * W[vid_n, d, k]
// N=400000, D=64, K=13, V=128.
//
// SINGLE persistent kernel, single co-resident wave:
//  Phase A: weight transpose + per-block smem-rank histogram (ranks in regs)
//  barrier1
//  Phase S: block v scans video v's count row -> per-block bases (O(G*V))
//  barrier2
//  Phase C: own bases + 32-padded segment scan + scatter to g_sorted
//  barrier3
//  Phase B: half-warp scheme — lane owns 4 output cols, halves take
//           alternate j; basis broadcast via __shfl_sync (R12: killed the
//           L1 wall). R12 residual = 28% issue efficiency from the
//           SHFL(26) -> FFMA2-chain(24) serial path at 3.3 warps/SMSP;
//           fix = manual x2 unroll of the j-loop so two independent
//           shfl batches + FMA chains are in flight per warp.

static constexpr int D  = 64;
static constexpr int K  = 13;
static constexpr int MAXV = 256;
static constexpr int SORT_CAP = 1 << 20;
static constexpr int GMAX = 1024;
static constexpr int TPB  = 256;
static constexpr int NU   = 4;     // int4 slots per thread in phase A

__device__ float g_wt[MAXV * K * D];
__device__ int   g_cnt[MAXV * GMAX];    // [v][b]
__device__ int   g_base[GMAX * MAXV];   // [b][v] scatter bases (pre-segoff)
__device__ int   g_segtot[MAXV];
__device__ int   g_sorted[SORT_CAP];    // never-written pad slots stay 0
__device__ int   g_bar, g_fin;

typedef unsigned long long ull;

__device__ __forceinline__ ull ffma2u(ull a, ull b, ull c) {
    ull d;
    asm("fma.rn.f32x2 %0, %1, %2, %3;" : "=l"(d) : "l"(a), "l"(b), "l"(c));
    return d;
}
__device__ __forceinline__ ull fmul2u(ull a, ull b) {
    ull d;
    asm("mul.rn.f32x2 %0, %1, %2;" : "=l"(d) : "l"(a), "l"(b));
    return d;
}
__device__ __forceinline__ ull fadd2u(ull a, ull b) {
    ull d;
    asm("add.rn.f32x2 %0, %1, %2;" : "=l"(d) : "l"(a), "l"(b));
    return d;
}
__device__ __forceinline__ ull splat2(float x) {
    ull r;
    asm("mov.b64 %0, {%1, %1};" : "=l"(r) : "f"(x));
    return r;
}

__device__ __forceinline__ void grid_barrier(int tid, int target) {
    __threadfence();
    __syncthreads();
    if (tid == 0) {
        atomicAdd(&g_bar, 1);
        volatile int* vb = &g_bar;
        while (*vb < target) __nanosleep(32);
    }
    __syncthreads();
}

__global__ void __launch_bounds__(TPB, 2)
k_all(const float* __restrict__ w, const int* __restrict__ vids,
      const float* __restrict__ times, float* __restrict__ out,
      int N, int V, int tile, int G) {
    __shared__ int s_rk[MAXV];        // rank counters -> scan scratch
    __shared__ int s_base[MAXV];      // this block's scatter bases
    __shared__ int s_start[MAXV + 1]; // padded segment starts (+ total)
    __shared__ int s_end[MAXV];       // real segment ends
    __shared__ int s_scan[TPB];       // phase-S block-scan scratch

    const int tid = threadIdx.x, b = blockIdx.x;
    for (int i = tid; i < MAXV; i += TPB) s_rk[i] = 0;
    __syncthreads();

    // ---- Phase A: transpose [v][d][k] -> [v][k][d] ----
    const int total = V * D * K;
    for (int i = b * TPB + tid; i < total; i += G * TPB) {
        int k = i % K;
        int d = (i / K) % D;
        int v = i / (K * D);
        g_wt[(v * K + k) * D + d] = w[i];
    }

    // ---- Phase A: histogram, ranks held in registers ----
    const int start = b * tile;               // tile is 4-aligned
    const int end   = min(start + tile, N);
    const int s4 = start >> 2, e4 = end >> 2;
    int4 q[NU]; int rk[NU][4]; bool hv[NU];
#pragma unroll
    for (int u = 0; u < NU; u++) {
        const int i4 = s4 + u * TPB + tid;
        hv[u] = (i4 < e4);
        if (hv[u]) {
            q[u] = reinterpret_cast<const int4*>(vids)[i4];
            rk[u][0] = atomicAdd(&s_rk[q[u].x], 1);
            rk[u][1] = atomicAdd(&s_rk[q[u].y], 1);
            rk[u][2] = atomicAdd(&s_rk[q[u].z], 1);
            rk[u][3] = atomicAdd(&s_rk[q[u].w], 1);
        }
    }
    int tval = -1, trk = 0;
    const int ti = (e4 << 2) + tid;
    if (ti < end) { tval = vids[ti]; trk = atomicAdd(&s_rk[tval], 1); }
    __syncthreads();

    for (int i = tid; i < V; i += TPB)
        g_cnt[i * GMAX + b] = s_rk[i];

    grid_barrier(tid, G);

    // ---- Phase S: block v scans video v's count row (cooperative) ----
    for (int v = b; v < V; v += G) {
        int4 c = make_int4(0, 0, 0, 0);
        const int bb = tid * 4;
        if (bb < G)
            c = *reinterpret_cast<const int4*>(g_cnt + v * GMAX + bb);
        const int lsum = c.x + c.y + c.z + c.w;
        s_scan[tid] = lsum;
        __syncthreads();
        for (int s = 1; s < TPB; s <<= 1) {       // inclusive block scan
            int a = (tid >= s) ? s_scan[tid - s] : 0;
            __syncthreads();
            s_scan[tid] += a;
            __syncthreads();
        }
        int excl = s_scan[tid] - lsum;
        if (bb < G) {
            g_base[(bb    ) * MAXV + v] = excl;
            g_base[(bb + 1) * MAXV + v] = excl + c.x;
            g_base[(bb + 2) * MAXV + v] = excl + c.x + c.y;
            g_base[(bb + 3) * MAXV + v] = excl + c.x + c.y + c.z;
        }
        if (tid == TPB - 1) g_segtot[v] = s_scan[tid];
        __syncthreads();
    }

    grid_barrier(tid, 2 * G);

    // ---- Phase C: own bases + padded segment scan + scatter ----
    int totv = 0;
    if (tid < MAXV) {
        totv = (tid < V) ? g_segtot[tid] : 0;
        s_rk[tid] = (totv + 31) & ~31;
    }
    __syncthreads();
    for (int s = 1; s < MAXV; s <<= 1) {          // inclusive scan over videos
        int a = (tid < MAXV && tid >= s) ? s_rk[tid - s] : 0;
        __syncthreads();
        if (tid < MAXV) s_rk[tid] += a;
        __syncthreads();
    }
    if (tid < MAXV) {
        const int pad = (totv + 31) & ~31;
        const int segoff = s_rk[tid] - pad;       // exclusive padded offset
        s_start[tid] = segoff;
        s_end[tid]   = segoff + totv;
        if (tid < V) s_base[tid] = segoff + g_base[b * MAXV + tid];
        if (tid == MAXV - 1) s_start[MAXV] = s_rk[tid];
    }
    __syncthreads();
    const int NC = s_start[MAXV] >> 5;

#pragma unroll
    for (int u = 0; u < NU; u++) {
        if (hv[u]) {
            const int base = (s4 + u * TPB + tid) << 2;
            g_sorted[s_base[q[u].x] + rk[u][0]] = base;
            g_sorted[s_base[q[u].y] + rk[u][1]] = base + 1;
            g_sorted[s_base[q[u].z] + rk[u][2]] = base + 2;
            g_sorted[s_base[q[u].w] + rk[u][3]] = base + 3;
        }
    }
    if (tval >= 0) g_sorted[s_base[tval] + trk] = ti;

    grid_barrier(tid, 3 * G);

    // ---- Phase B: half-warp, 4 cols/lane, shfl broadcast, x2 unroll ----
    const int lane = tid & 31;
    const int wib  = tid >> 5;
    const int half = lane >> 4;            // 0: even j, 1: odd j
    const int c4   = (lane & 15) * 4;      // 4 owned output columns
    const int gwarp = b * 8 + wib;
    const int TW = G * 8;
    const int L = (NC + TW - 1) / TW;
    const int cbeg = gwarp * L;
    const int cend = min(cbeg + L, NC);

    if (cbeg < cend) {
        int v = 0;
        {
            const int pos = cbeg * 32;
#pragma unroll
            for (int step = 128; step; step >>= 1) {
                const int nv = v + step;
                if (nv <= MAXV - 1 && s_start[nv] <= pos) v = nv;
            }
        }
        int vprev = -1;
        ull wA[K], wB[K];

        for (int c = cbeg; c < cend; c++) {
            const int pos = c * 32;
            while (pos >= s_start[v + 1]) v++;     // warp-uniform walk

            const int idx = g_sorted[pos + lane];  // pad slots are 0 (valid)
            if (v != vprev) {
                const float* wp = g_wt + v * (K * D) + c4;
#pragma unroll
                for (int k = 0; k < K; k++) {
                    ulonglong2 u =
                        *reinterpret_cast<const ulonglong2*>(wp + k * D);
                    wA[k] = u.x; wB[k] = u.y;
                }
                vprev = v;
            }

            // basis for this lane's own n, kept in registers
            const float t = times[idx];
            const float ang = t * 3.14159265358979323846f;
            float s1, q1; __sincosf(ang, &s1, &q1);
            const float s2 = 2.f * s1 * q1, q2 = fmaf(q1, q1, -s1 * s1);
            const float s3 = 2.f * s2 * q2, q3 = fmaf(q2, q2, -s2 * s2);
            const float s4b = 2.f * s3 * q3, q4 = fmaf(q3, q3, -s3 * s3);
            const float s5 = 2.f * s4b * q4, q5 = fmaf(q4, q4, -s4b * s4b);
            const float s6 = 2.f * s5 * q5, q6 = fmaf(q5, q5, -s5 * s5);

            const unsigned m = 0xffffffffu;
            const int jmax  = min(32, s_end[v] - pos);   // >= 1, warp-uniform
            const int jpmax = (jmax + 1) >> 1;

            // one step = one n per half-warp
            auto stepf = [&](int j0) {
                const int nn = __shfl_sync(m, idx, j0);
                const ull B1  = splat2(__shfl_sync(m, s1,  j0));
                const ull B2  = splat2(__shfl_sync(m, s2,  j0));
                const ull B3  = splat2(__shfl_sync(m, s3,  j0));
                const ull B4  = splat2(__shfl_sync(m, s4b, j0));
                const ull B5  = splat2(__shfl_sync(m, s5,  j0));
                const ull B6  = splat2(__shfl_sync(m, s6,  j0));
                const ull B7  = splat2(__shfl_sync(m, q1,  j0));
                const ull B8  = splat2(__shfl_sync(m, q2,  j0));
                const ull B9  = splat2(__shfl_sync(m, q3,  j0));
                const ull B10 = splat2(__shfl_sync(m, q4,  j0));
                const ull B11 = splat2(__shfl_sync(m, q5,  j0));
                const ull B12 = splat2(__shfl_sync(m, q6,  j0));

                ull a0 = ffma2u(B1, wA[1], wA[0]);       // basis[0] == 1
                ull a1 = fmul2u(B2, wA[2]);
                a0 = ffma2u(B3,  wA[3],  a0);
                a1 = ffma2u(B4,  wA[4],  a1);
                a0 = ffma2u(B5,  wA[5],  a0);
                a1 = ffma2u(B6,  wA[6],  a1);
                a0 = ffma2u(B7,  wA[7],  a0);
                a1 = ffma2u(B8,  wA[8],  a1);
                a0 = ffma2u(B9,  wA[9],  a0);
                a1 = ffma2u(B10, wA[10], a1);
                a0 = ffma2u(B11, wA[11], a0);
                a1 = ffma2u(B12, wA[12], a1);
                ull b0 = ffma2u(B1, wB[1], wB[0]);
                ull b1 = fmul2u(B2, wB[2]);
                b0 = ffma2u(B3,  wB[3],  b0);
                b1 = ffma2u(B4,  wB[4],  b1);
                b0 = ffma2u(B5,  wB[5],  b0);
                b1 = ffma2u(B6,  wB[6],  b1);
                b0 = ffma2u(B7,  wB[7],  b0);
                b1 = ffma2u(B8,  wB[8],  b1);
                b0 = ffma2u(B9,  wB[9],  b0);
                b1 = ffma2u(B10, wB[10], b1);
                b0 = ffma2u(B11, wB[11], b0);
                b1 = ffma2u(B12, wB[12], b1);
                if (j0 < jmax) {
                    *reinterpret_cast<ulonglong2*>(out + (long)nn * D + c4) =
                        make_ulonglong2(fadd2u(a0, a1), fadd2u(b0, b1));
                }
            };

            int jp = 0;
            for (; jp + 2 <= jpmax; jp += 2) {     // x2 unroll: 2 independent
                stepf(2 * jp + half);              // shfl batches + FMA chains
                stepf(2 * jp + 2 + half);          // in flight per warp
            }
            if (jp < jpmax) stepf(2 * jp + half);
        }
    }

    // ---- exit ticket: reset barrier counters for next graph replay ----
    __threadfence();
    if (tid == 0) {
        if (atomicAdd(&g_fin, 1) == G - 1) { g_bar = 0; g_fin = 0; }
    }
}

extern "C" void kernel_launch(void* const* d_in, const int* in_sizes, int n_in,
                              void* d_out, int out_size) {
    const float* times   = (const float*)d_in[0];
    const int*   vids    = (const int*)d_in[1];
    const float* weights = (const float*)d_in[2];
    float*       out     = (float*)d_out;

    const int N = in_sizes[0];
    int V = in_sizes[2] / (D * K);
    if (V > MAXV) V = MAXV;

    int dev = 0;
    cudaGetDevice(&dev);
    int sms = 148;
    cudaDeviceGetAttribute(&sms, cudaDevAttrMultiProcessorCount, dev);
    int nb = 0;
    cudaOccupancyMaxActiveBlocksPerMultiprocessor(&nb, k_all, TPB, 0);
    if (nb < 1) nb = 1;
    int G = nb * sms;
    if (G > GMAX) G = GMAX;
    G &= ~3;                                  // multiple of 4 (int4 row reads)

    const int tile = (((N + G - 1) / G) + 3) & ~3;   // 4-aligned
    k_all<<<G, TPB>>>(weights, vids, times, out, N, V, tile, G);
}

// round 14
// speedup vs baseline: 1.1615x; 1.0124x over previous
#include <cuda_runtime.h>

// VideoEmbedding: out[n,d] = sum_k basis(t_n)[k] * W[vid_n, d, k]
// N=400000, D=64, K=13, V=128.
//
// SINGLE persistent kernel, single co-resident wave:
//  Phase A: weight transpose + per-block smem-rank histogram (ranks in regs)
//  barrier1
//  Phase S: block v scans video v's count row -> per-block bases (O(G*V))
//  barrier2
//  Phase C: own bases + 32-padded segment scan + scatter to g_sorted
//  barrier3
//  Phase B: half-warp scheme — lane owns 4 output cols, halves take
//           alternate j; basis broadcast via __shfl_sync.
//           R13 residual: per-chunk serial prologue g_sorted -> times[idx]
//           (two dependent L2 trips ~550cyc) exposed at 3.5 warps/SMSP.
//           Fix: software-pipeline the NEXT chunk's idx/times loads under
//           the current chunk's j-loop. x2 unroll dropped (reg-capped,
//           proven ineffective) to make register room for the prefetch.

static constexpr int D  = 64;
static constexpr int K  = 13;
static constexpr int MAXV = 256;
static constexpr int SORT_CAP = 1 << 20;
static constexpr int GMAX = 1024;
static constexpr int TPB  = 256;
static constexpr int NU   = 4;     // int4 slots per thread in phase A

__device__ float g_wt[MAXV * K * D];
__device__ int   g_cnt[MAXV * GMAX];    // [v][b]
__device__ int   g_base[GMAX * MAXV];   // [b][v] scatter bases (pre-segoff)
__device__ int   g_segtot[MAXV];
__device__ int   g_sorted[SORT_CAP];    // never-written pad slots stay 0
__device__ int   g_bar, g_fin;

typedef unsigned long long ull;

__device__ __forceinline__ ull ffma2u(ull a, ull b, ull c) {
    ull d;
    asm("fma.rn.f32x2 %0, %1, %2, %3;" : "=l"(d) : "l"(a), "l"(b), "l"(c));
    return d;
}
__device__ __forceinline__ ull fmul2u(ull a, ull b) {
    ull d;
    asm("mul.rn.f32x2 %0, %1, %2;" : "=l"(d) : "l"(a), "l"(b));
    return d;
}
__device__ __forceinline__ ull fadd2u(ull a, ull b) {
    ull d;
    asm("add.rn.f32x2 %0, %1, %2;" : "=l"(d) : "l"(a), "l"(b));
    return d;
}
__device__ __forceinline__ ull splat2(float x) {
    ull r;
    asm("mov.b64 %0, {%1, %1};" : "=l"(r) : "f"(x));
    return r;
}

__device__ __forceinline__ void grid_barrier(int tid, int target) {
    __threadfence();
    __syncthreads();
    if (tid == 0) {
        atomicAdd(&g_bar, 1);
        volatile int* vb = &g_bar;
        while (*vb < target) __nanosleep(32);
    }
    __syncthreads();
}

__global__ void __launch_bounds__(TPB, 2)
k_all(const float* __restrict__ w, const int* __restrict__ vids,
      const float* __restrict__ times, float* __restrict__ out,
      int N, int V, int tile, int G) {
    __shared__ int s_rk[MAXV];        // rank counters -> scan scratch
    __shared__ int s_base[MAXV];      // this block's scatter bases
    __shared__ int s_start[MAXV + 1]; // padded segment starts (+ total)
    __shared__ int s_end[MAXV];       // real segment ends
    __shared__ int s_scan[TPB];       // phase-S block-scan scratch

    const int tid = threadIdx.x, b = blockIdx.x;
    for (int i = tid; i < MAXV; i += TPB) s_rk[i] = 0;
    __syncthreads();

    // ---- Phase A: transpose [v][d][k] -> [v][k][d] ----
    const int total = V * D * K;
    for (int i = b * TPB + tid; i < total; i += G * TPB) {
        int k = i % K;
        int d = (i / K) % D;
        int v = i / (K * D);
        g_wt[(v * K + k) * D + d] = w[i];
    }

    // ---- Phase A: histogram, ranks held in registers ----
    const int start = b * tile;               // tile is 4-aligned
    const int end   = min(start + tile, N);
    const int s4 = start >> 2, e4 = end >> 2;
    int4 q[NU]; int rk[NU][4]; bool hv[NU];
#pragma unroll
    for (int u = 0; u < NU; u++) {
        const int i4 = s4 + u * TPB + tid;
        hv[u] = (i4 < e4);
        if (hv[u]) {
            q[u] = reinterpret_cast<const int4*>(vids)[i4];
            rk[u][0] = atomicAdd(&s_rk[q[u].x], 1);
            rk[u][1] = atomicAdd(&s_rk[q[u].y], 1);
            rk[u][2] = atomicAdd(&s_rk[q[u].z], 1);
            rk[u][3] = atomicAdd(&s_rk[q[u].w], 1);
        }
    }
    int tval = -1, trk = 0;
    const int ti = (e4 << 2) + tid;
    if (ti < end) { tval = vids[ti]; trk = atomicAdd(&s_rk[tval], 1); }
    __syncthreads();

    for (int i = tid; i < V; i += TPB)
        g_cnt[i * GMAX + b] = s_rk[i];

    grid_barrier(tid, G);

    // ---- Phase S: block v scans video v's count row (cooperative) ----
    for (int v = b; v < V; v += G) {
        int4 c = make_int4(0, 0, 0, 0);
        const int bb = tid * 4;
        if (bb < G)
            c = *reinterpret_cast<const int4*>(g_cnt + v * GMAX + bb);
        const int lsum = c.x + c.y + c.z + c.w;
        s_scan[tid] = lsum;
        __syncthreads();
        for (int s = 1; s < TPB; s <<= 1) {       // inclusive block scan
            int a = (tid >= s) ? s_scan[tid - s] : 0;
            __syncthreads();
            s_scan[tid] += a;
            __syncthreads();
        }
        int excl = s_scan[tid] - lsum;
        if (bb < G) {
            g_base[(bb    ) * MAXV + v] = excl;
            g_base[(bb + 1) * MAXV + v] = excl + c.x;
            g_base[(bb + 2) * MAXV + v] = excl + c.x + c.y;
            g_base[(bb + 3) * MAXV + v] = excl + c.x + c.y + c.z;
        }
        if (tid == TPB - 1) g_segtot[v] = s_scan[tid];
        __syncthreads();
    }

    grid_barrier(tid, 2 * G);

    // ---- Phase C: own bases + padded segment scan + scatter ----
    int totv = 0;
    if (tid < MAXV) {
        totv = (tid < V) ? g_segtot[tid] : 0;
        s_rk[tid] = (totv + 31) & ~31;
    }
    __syncthreads();
    for (int s = 1; s < MAXV; s <<= 1) {          // inclusive scan over videos
        int a = (tid < MAXV && tid >= s) ? s_rk[tid - s] : 0;
        __syncthreads();
        if (tid < MAXV) s_rk[tid] += a;
        __syncthreads();
    }
    if (tid < MAXV) {
        const int pad = (totv + 31) & ~31;
        const int segoff = s_rk[tid] - pad;       // exclusive padded offset
        s_start[tid] = segoff;
        s_end[tid]   = segoff + totv;
        if (tid < V) s_base[tid] = segoff + g_base[b * MAXV + tid];
        if (tid == MAXV - 1) s_start[MAXV] = s_rk[tid];
    }
    __syncthreads();
    const int NC = s_start[MAXV] >> 5;

#pragma unroll
    for (int u = 0; u < NU; u++) {
        if (hv[u]) {
            const int base = (s4 + u * TPB + tid) << 2;
            g_sorted[s_base[q[u].x] + rk[u][0]] = base;
            g_sorted[s_base[q[u].y] + rk[u][1]] = base + 1;
            g_sorted[s_base[q[u].z] + rk[u][2]] = base + 2;
            g_sorted[s_base[q[u].w] + rk[u][3]] = base + 3;
        }
    }
    if (tval >= 0) g_sorted[s_base[tval] + trk] = ti;

    grid_barrier(tid, 3 * G);

    // ---- Phase B: half-warp, 4 cols/lane, shfl broadcast, chunk prefetch --
    const int lane = tid & 31;
    const int wib  = tid >> 5;
    const int half = lane >> 4;            // 0: even j, 1: odd j
    const int c4   = (lane & 15) * 4;      // 4 owned output columns
    const int gwarp = b * 8 + wib;
    const int TW = G * 8;
    const int L = (NC + TW - 1) / TW;
    const int cbeg = gwarp * L;
    const int cend = min(cbeg + L, NC);

    if (cbeg < cend) {
        int v = 0;
        {
            const int pos = cbeg * 32;
#pragma unroll
            for (int step = 128; step; step >>= 1) {
                const int nv = v + step;
                if (nv <= MAXV - 1 && s_start[nv] <= pos) v = nv;
            }
        }
        int vprev = -1;
        ull wA[K], wB[K];

        // prologue loads for the first chunk
        int   idx = g_sorted[cbeg * 32 + lane];   // pad slots are 0 (valid)
        float t   = times[idx];

        for (int c = cbeg; c < cend; c++) {
            const int pos = c * 32;
            while (pos >= s_start[v + 1]) v++;     // warp-uniform walk

            if (v != vprev) {
                const float* wp = g_wt + v * (K * D) + c4;
#pragma unroll
                for (int k = 0; k < K; k++) {
                    ulonglong2 u =
                        *reinterpret_cast<const ulonglong2*>(wp + k * D);
                    wA[k] = u.x; wB[k] = u.y;
                }
                vprev = v;
            }

            // basis for this lane's own n, kept in registers
            const float ang = t * 3.14159265358979323846f;
            float s1, q1; __sincosf(ang, &s1, &q1);
            const float s2 = 2.f * s1 * q1, q2 = fmaf(q1, q1, -s1 * s1);
            const float s3 = 2.f * s2 * q2, q3 = fmaf(q2, q2, -s2 * s2);
            const float s4b = 2.f * s3 * q3, q4 = fmaf(q3, q3, -s3 * s3);
            const float s5 = 2.f * s4b * q4, q5 = fmaf(q4, q4, -s4b * s4b);
            const float s6 = 2.f * s5 * q5, q6 = fmaf(q5, q5, -s5 * s5);

            // software pipeline: issue next chunk's dependent load chain
            // now, so its ~550cyc latency hides under this chunk's j-loop
            int   idx_nx = 0;
            float t_nx   = 0.f;
            if (c + 1 < cend) {
                idx_nx = g_sorted[pos + 32 + lane];
                t_nx   = times[idx_nx];
            }

            const unsigned m = 0xffffffffu;
            const int jmax  = min(32, s_end[v] - pos);   // >= 1, warp-uniform
            const int jpmax = (jmax + 1) >> 1;

            for (int jp = 0; jp < jpmax; jp++) {
                const int j0 = 2 * jp + half;            // per-half source n
                const int nn = __shfl_sync(m, idx, j0);
                const ull B1  = splat2(__shfl_sync(m, s1,  j0));
                const ull B2  = splat2(__shfl_sync(m, s2,  j0));
                const ull B3  = splat2(__shfl_sync(m, s3,  j0));
                const ull B4  = splat2(__shfl_sync(m, s4b, j0));
                const ull B5  = splat2(__shfl_sync(m, s5,  j0));
                const ull B6  = splat2(__shfl_sync(m, s6,  j0));
                const ull B7  = splat2(__shfl_sync(m, q1,  j0));
                const ull B8  = splat2(__shfl_sync(m, q2,  j0));
                const ull B9  = splat2(__shfl_sync(m, q3,  j0));
                const ull B10 = splat2(__shfl_sync(m, q4,  j0));
                const ull B11 = splat2(__shfl_sync(m, q5,  j0));
                const ull B12 = splat2(__shfl_sync(m, q6,  j0));

                ull a0 = ffma2u(B1, wA[1], wA[0]);       // basis[0] == 1
                ull a1 = fmul2u(B2, wA[2]);
                a0 = ffma2u(B3,  wA[3],  a0);
                a1 = ffma2u(B4,  wA[4],  a1);
                a0 = ffma2u(B5,  wA[5],  a0);
                a1 = ffma2u(B6,  wA[6],  a1);
                a0 = ffma2u(B7,  wA[7],  a0);
                a1 = ffma2u(B8,  wA[8],  a1);
                a0 = ffma2u(B9,  wA[9],  a0);
                a1 = ffma2u(B10, wA[10], a1);
                a0 = ffma2u(B11, wA[11], a0);
                a1 = ffma2u(B12, wA[12], a1);
                ull b0 = ffma2u(B1, wB[1], wB[0]);
                ull b1 = fmul2u(B2, wB[2]);
                b0 = ffma2u(B3,  wB[3],  b0);
                b1 = ffma2u(B4,  wB[4],  b1);
                b0 = ffma2u(B5,  wB[5],  b0);
                b1 = ffma2u(B6,  wB[6],  b1);
                b0 = ffma2u(B7,  wB[7],  b0);
                b1 = ffma2u(B8,  wB[8],  b1);
                b0 = ffma2u(B9,  wB[9],  b0);
                b1 = ffma2u(B10, wB[10], b1);
                b0 = ffma2u(B11, wB[11], b0);
                b1 = ffma2u(B12, wB[12], b1);
                if (j0 < jmax) {
                    *reinterpret_cast<ulonglong2*>(out + (long)nn * D + c4) =
                        make_ulonglong2(fadd2u(a0, a1), fadd2u(b0, b1));
                }
            }

            idx = idx_nx;          // rotate pipeline
            t   = t_nx;
        }
    }

    // ---- exit ticket: reset barrier counters for next graph replay ----
    __threadfence();
    if (tid == 0) {
        if (atomicAdd(&g_fin, 1) == G - 1) { g_bar = 0; g_fin = 0; }
    }
}

extern "C" void kernel_launch(void* const* d_in, const int* in_sizes, int n_in,
                              void* d_out, int out_size) {
    const float* times   = (const float*)d_in[0];
    const int*   vids    = (const int*)d_in[1];
    const float* weights = (const float*)d_in[2];
    float*       out     = (float*)d_out;

    const int N = in_sizes[0];
    int V = in_sizes[2] / (D * K);
    if (V > MAXV) V = MAXV;

    int dev = 0;
    cudaGetDevice(&dev);
    int sms = 148;
    cudaDeviceGetAttribute(&sms, cudaDevAttrMultiProcessorCount, dev);
    int nb = 0;
    cudaOccupancyMaxActiveBlocksPerMultiprocessor(&nb, k_all, TPB, 0);
    if (nb < 1) nb = 1;
    int G = nb * sms;
    if (G > GMAX) G = GMAX;
    G &= ~3;                                  // multiple of 4 (int4 row reads)

    const int tile = (((N + G - 1) / G) + 3) & ~3;   // 4-aligned
    k_all<<<G, TPB>>>(weights, vids, times, out, N, V, tile, G);
}